// round 17
// baseline (speedup 1.0000x reference)
#include <cuda_runtime.h>
#include <cuda_fp16.h>
#include <math.h>
#include <stdint.h>

#define BATCH 4
#define SEQ   2048
#define DIN   1024
#define DOUT  1024

#define BM 128
#define BN 128
#define BK 64       // K-chunk per pipeline stage (4 x 16 K-steps, frag ping-pong)
#define NTH 128     // 4 warps: 2 (m) x 2 (n), 64x64 warp tiles
#define NSTG 3      // smem pipeline stages

// fp16 scratch
__device__ __half g_xh[BATCH * SEQ * DIN];
__device__ __half g_wqh[DIN * DOUT];
__device__ __half g_wkh[DIN * DOUT];
__device__ __half g_wvh[DIN * DOUT];
__device__ __half g_q[BATCH * SEQ * DOUT];
__device__ __half g_k[BATCH * SEQ * DOUT];
__device__ __half g_v[BATCH * SEQ * DOUT];
__device__ __half g_sh[(size_t)BATCH * SEQ * SEQ];  // unnormalized exp(scores)
__device__ float  g_inv[BATCH * SEQ];               // 1 / rowsum

extern __shared__ char smem_raw[];

// Smem geometry (halves)
#define A_LDH 72
#define B_LDH 136
#define A_SZH (BM * A_LDH)        // 9216 halves (18432 B)
#define B_SZH (BK * B_LDH)        // 8704 halves (17408 B)
#define STAGE_AB (A_SZH + B_SZH)  // 17920 halves (35840 B)
#define STAGE_AA (2 * A_SZH)      // 18432 halves (36864 B)

// ---------------------------------------------------------------------------
__device__ __forceinline__ uint32_t sptr(const void* p) {
    return (uint32_t)__cvta_generic_to_shared(p);
}
__device__ __forceinline__ void ldsm4(uint32_t r[4], uint32_t a) {
    asm volatile("ldmatrix.sync.aligned.m8n8.x4.shared.b16 {%0,%1,%2,%3}, [%4];"
                 : "=r"(r[0]), "=r"(r[1]), "=r"(r[2]), "=r"(r[3]) : "r"(a));
}
__device__ __forceinline__ void ldsm4t(uint32_t r[4], uint32_t a) {
    asm volatile("ldmatrix.sync.aligned.m8n8.x4.trans.shared.b16 {%0,%1,%2,%3}, [%4];"
                 : "=r"(r[0]), "=r"(r[1]), "=r"(r[2]), "=r"(r[3]) : "r"(a));
}
__device__ __forceinline__ void mma_f16s(float c[4], const uint32_t a[4], const uint32_t b[2]) {
    asm volatile(
        "mma.sync.aligned.m16n8k16.row.col.f32.f16.f16.f32 "
        "{%0,%1,%2,%3}, {%4,%5,%6,%7}, {%8,%9}, {%0,%1,%2,%3};"
        : "+f"(c[0]), "+f"(c[1]), "+f"(c[2]), "+f"(c[3])
        : "r"(a[0]), "r"(a[1]), "r"(a[2]), "r"(a[3]), "r"(b[0]), "r"(b[1]));
}
__device__ __forceinline__ void cp16(__half* dst_smem, const __half* src) {
    uint32_t d = sptr(dst_smem);
    asm volatile("cp.async.cg.shared.global [%0], [%1], 16;\n" :: "r"(d), "l"(src));
}
__device__ __forceinline__ void cp_commit() { asm volatile("cp.async.commit_group;\n"); }
__device__ __forceinline__ void cp_wait1()  { asm volatile("cp.async.wait_group 1;\n"); }

__device__ __forceinline__ void pf_a(__half* S, const __half* __restrict__ src, int lda, int tid) {
#pragma unroll
    for (int i = 0; i < 8; i++) {
        int u = tid + i * NTH;
        int r = u >> 3;
        int col = (u & 7) * 8;
        cp16(S + r * A_LDH + col, src + (size_t)r * lda + col);
    }
}
__device__ __forceinline__ void pf_b(__half* S, const __half* __restrict__ src, int ldb, int tid) {
#pragma unroll
    for (int i = 0; i < 8; i++) {
        int u = tid + i * NTH;
        int r = u >> 4;
        int col = (u & 15) * 8;
        cp16(S + r * B_LDH + col, src + (size_t)r * ldb + col);
    }
}

// --- single K=16 step fragment loaders ---
__device__ __forceinline__ void la16(const __half* As, uint32_t a[4][4], int wm, int lane, int kk) {
#pragma unroll
    for (int mi = 0; mi < 4; mi++) {
        int r = wm * 64 + mi * 16 + (lane & 15);
        int c = kk + 8 * (lane >> 4);
        ldsm4(a[mi], sptr(&As[r * A_LDH + c]));
    }
}
__device__ __forceinline__ void lb16_nmaj(const __half* Bs, uint32_t b[8][2], int wn, int lane, int kk) {
    const int g = lane >> 3;
#pragma unroll
    for (int np = 0; np < 4; np++) {
        int row = wn * 64 + np * 16 + (g >> 1) * 8 + (lane & 7);
        int col = kk + (g & 1) * 8;
        uint32_t r4[4];
        ldsm4(r4, sptr(&Bs[row * A_LDH + col]));
        b[2 * np][0] = r4[0]; b[2 * np][1] = r4[1];
        b[2 * np + 1][0] = r4[2]; b[2 * np + 1][1] = r4[3];
    }
}
__device__ __forceinline__ void lb16_kmaj(const __half* Bs, uint32_t b[8][2], int wn, int lane, int kk) {
    const int g = lane >> 3;
#pragma unroll
    for (int np = 0; np < 4; np++) {
        int row = kk + (g & 1) * 8 + (lane & 7);
        int col = wn * 64 + np * 16 + (g >> 1) * 8;
        uint32_t r4[4];
        ldsm4t(r4, sptr(&Bs[row * B_LDH + col]));
        b[2 * np][0] = r4[0]; b[2 * np][1] = r4[1];
        b[2 * np + 1][0] = r4[2]; b[2 * np + 1][1] = r4[3];
    }
}
__device__ __forceinline__ void mma16(float acc[4][8][4], uint32_t a[4][4], uint32_t b[8][2]) {
#pragma unroll
    for (int mi = 0; mi < 4; mi++)
#pragma unroll
        for (int ni = 0; ni < 8; ni++)
            mma_f16s(acc[mi][ni], a[mi], b[ni]);
}

#define COMPUTE64(sc, scB, BKIND)                                              \
    do {                                                                       \
        uint32_t aE[4][4], bE[8][2], aO[4][4], bO[8][2];                       \
        la16(sc, aE, wm, lane, 0);                                             \
        if (BKIND) lb16_nmaj(scB, bE, wn, lane, 0);                            \
        else       lb16_kmaj(scB, bE, wn, lane, 0);                            \
        la16(sc, aO, wm, lane, 16);                                            \
        if (BKIND) lb16_nmaj(scB, bO, wn, lane, 16);                           \
        else       lb16_kmaj(scB, bO, wn, lane, 16);                           \
        mma16(acc, aE, bE);                                                    \
        la16(sc, aE, wm, lane, 32);                                            \
        if (BKIND) lb16_nmaj(scB, bE, wn, lane, 32);                           \
        else       lb16_kmaj(scB, bE, wn, lane, 32);                           \
        mma16(acc, aO, bO);                                                    \
        la16(sc, aO, wm, lane, 48);                                            \
        if (BKIND) lb16_nmaj(scB, bO, wn, lane, 48);                           \
        else       lb16_kmaj(scB, bO, wn, lane, 48);                           \
        mma16(acc, aE, bE);                                                    \
        mma16(acc, aO, bO);                                                    \
    } while (0)

#define ZERO_ACC(acc)                                        \
    _Pragma("unroll") for (int _a = 0; _a < 4; _a++)         \
    _Pragma("unroll") for (int _b = 0; _b < 8; _b++)         \
    _Pragma("unroll") for (int _c = 0; _c < 4; _c++) acc[_a][_b][_c] = 0.0f;

// ---------------------------------------------------------------------------
// Converts: main handles x, Wq, Wk; aux handles Wv.
// ---------------------------------------------------------------------------
#define NX4 (BATCH * SEQ * DIN / 4)
#define NW4 (DIN * DOUT / 4)
__global__ __launch_bounds__(256)
void cvt_xqk(const float* __restrict__ x, const float* __restrict__ Wq,
             const float* __restrict__ Wk) {
    int i = blockIdx.x * 256 + threadIdx.x;
    const float* src;
    __half* dst;
    int j;
    if (i < NX4)               { src = x;  dst = g_xh;  j = i; }
    else {
        int k = i - NX4;
        if (k < NW4)           { src = Wq; dst = g_wqh; j = k; }
        else if (k < 2 * NW4)  { src = Wk; dst = g_wkh; j = k - NW4; }
        else return;
    }
    float4 v = ((const float4*)src)[j];
    ((__half2*)dst)[2 * j]     = __floats2half2_rn(v.x, v.y);
    ((__half2*)dst)[2 * j + 1] = __floats2half2_rn(v.z, v.w);
}
__global__ __launch_bounds__(256)
void cvt_wv(const float* __restrict__ Wv) {
    int j = blockIdx.x * 256 + threadIdx.x;
    if (j < NW4) {
        float4 v = ((const float4*)Wv)[j];
        ((__half2*)g_wvh)[2 * j]     = __floats2half2_rn(v.x, v.y);
        ((__half2*)g_wvh)[2 * j + 1] = __floats2half2_rn(v.z, v.w);
    }
}

// ---------------------------------------------------------------------------
// zero_upper: strictly-upper triangle of fp32 weights (from float4 boundary).
// weights_write covers [0, n4end); this covers [n4end, SEQ). Disjoint.
// ---------------------------------------------------------------------------
__global__ __launch_bounds__(256)
void zero_upper(float* __restrict__ weights) {
    const int row = blockIdx.x;
    const int i = row & (SEQ - 1);
    const int j40 = (((i + 1) + 3) & ~3) >> 2;
    float4* w4 = (float4*)(weights + (size_t)row * SEQ);
    const float4 z = make_float4(0.f, 0.f, 0.f, 0.f);
    for (int j4 = j40 + threadIdx.x; j4 < SEQ / 4; j4 += 256)
        w4[j4] = z;
}

// ---------------------------------------------------------------------------
// QKV projection; zbase selects starting weight (0=Q.., 2=V).
// ---------------------------------------------------------------------------
__global__ __launch_bounds__(NTH)
void qkv_kernel(int zbase) {
    __half* smem = (__half*)smem_raw;
    const int z = (int)blockIdx.z + zbase;
    const __half* W;
    __half* O;
    if (z == 0)      { W = g_wqh; O = g_q; }
    else if (z == 1) { W = g_wkh; O = g_k; }
    else             { W = g_wvh; O = g_v; }

    const int m0 = blockIdx.y * BM;
    const int n0 = blockIdx.x * BN;
    const int tid = threadIdx.x;
    const int warp = tid >> 5, lane = tid & 31;
    const int wm = warp >> 1, wn = warp & 1;

    const __half* Ab = g_xh + (size_t)m0 * DIN;
    const __half* Bb = W + n0;

    float acc[4][8][4];
    ZERO_ACC(acc);

    const int T = DIN / BK;   // 16
#pragma unroll
    for (int p = 0; p < 2; p++) {
        __half* st = smem + p * STAGE_AB;
        pf_a(st, Ab + p * BK, DIN, tid);
        pf_b(st + A_SZH, Bb + (size_t)p * BK * DOUT, DOUT, tid);
        cp_commit();
    }

    for (int t = 0; t < T; t++) {
        cp_wait1();
        __syncthreads();
        const __half* sc = smem + (t % NSTG) * STAGE_AB;
        COMPUTE64(sc, sc + A_SZH, 0);
        if (t + 2 < T) {
            __half* st = smem + ((t + 2) % NSTG) * STAGE_AB;
            pf_a(st, Ab + (t + 2) * BK, DIN, tid);
            pf_b(st + A_SZH, Bb + (size_t)(t + 2) * BK * DOUT, DOUT, tid);
        }
        cp_commit();
    }

    __half* C = O + (size_t)m0 * DOUT + n0;
    const int g = lane >> 2, tig = lane & 3;
#pragma unroll
    for (int mi = 0; mi < 4; mi++)
#pragma unroll
        for (int ni = 0; ni < 8; ni++) {
            int r = wm * 64 + mi * 16 + g;
            int c = wn * 64 + ni * 8 + 2 * tig;
            *(__half2*)(C + (size_t)r * DOUT + c) = __floats2half2_rn(acc[mi][ni][0], acc[mi][ni][1]);
            *(__half2*)(C + (size_t)(r + 8) * DOUT + c) = __floats2half2_rn(acc[mi][ni][2], acc[mi][ni][3]);
        }
}

// ---------------------------------------------------------------------------
// scores (per batch b): unnormalized exp -> g_sh; causal; fused exp.
// ---------------------------------------------------------------------------
__global__ __launch_bounds__(NTH)
void scores_kernel(int b) {
    const int by = (int)gridDim.y - 1 - (int)blockIdx.y;   // reversed
    if ((int)blockIdx.x > by) return;

    __half* smem = (__half*)smem_raw;
    const int m0 = by * BM;
    const int n0 = blockIdx.x * BN;
    const bool diag = ((int)blockIdx.x == by);
    const int tid = threadIdx.x;
    const int warp = tid >> 5, lane = tid & 31;
    const int wm = warp >> 1, wn = warp & 1;

    const __half* Q  = g_q + (size_t)b * SEQ * DOUT + (size_t)m0 * DOUT;
    const __half* Kp = g_k + (size_t)b * SEQ * DOUT + (size_t)n0 * DOUT;
    __half* Eout = g_sh + (size_t)b * SEQ * SEQ;

    float acc[4][8][4];
    ZERO_ACC(acc);

    const int T = DOUT / BK;   // 16
#pragma unroll
    for (int p = 0; p < 2; p++) {
        __half* st = smem + p * STAGE_AA;
        pf_a(st, Q + p * BK, DOUT, tid);
        pf_a(st + A_SZH, Kp + p * BK, DOUT, tid);
        cp_commit();
    }

    for (int t = 0; t < T; t++) {
        cp_wait1();
        __syncthreads();
        const __half* sc = smem + (t % NSTG) * STAGE_AA;
        COMPUTE64(sc, sc + A_SZH, 1);
        if (t + 2 < T) {
            __half* st = smem + ((t + 2) % NSTG) * STAGE_AA;
            pf_a(st, Q + (t + 2) * BK, DOUT, tid);
            pf_a(st + A_SZH, Kp + (t + 2) * BK, DOUT, tid);
        }
        cp_commit();
    }

    const float SC = 0.03125f;
    const int g = lane >> 2, tig = lane & 3;
#pragma unroll
    for (int mi = 0; mi < 4; mi++)
#pragma unroll
        for (int ni = 0; ni < 8; ni++) {
            int r = wm * 64 + mi * 16 + g;
            int c = wn * 64 + ni * 8 + 2 * tig;
            float e0 = __expf(acc[mi][ni][0] * SC);
            float e1 = __expf(acc[mi][ni][1] * SC);
            float e2 = __expf(acc[mi][ni][2] * SC);
            float e3 = __expf(acc[mi][ni][3] * SC);
            if (diag) {
                if (c     > r)     e0 = 0.0f;
                if (c + 1 > r)     e1 = 0.0f;
                if (c     > r + 8) e2 = 0.0f;
                if (c + 1 > r + 8) e3 = 0.0f;
            }
            *(__half2*)(Eout + (size_t)(m0 + r) * SEQ + n0 + c) = __floats2half2_rn(e0, e1);
            *(__half2*)(Eout + (size_t)(m0 + r + 8) * SEQ + n0 + c) = __floats2half2_rn(e2, e3);
        }
}

// ---------------------------------------------------------------------------
// norm_light (per batch): rowsum of e -> g_inv. No weights write.
// ---------------------------------------------------------------------------
__global__ __launch_bounds__(256)
void norm_light(int b) {
    const int i = blockIdx.x;
    const int row = b * SEQ + i;
    const __half* e = g_sh + (size_t)row * SEQ;
    const int tid = threadIdx.x;
    const int n = i + 1;

    float lsum = 0.0f;
#pragma unroll
    for (int t = 0; t < 8; t++) {
        int j = tid + t * 256;
        if (j < n) lsum += __half2float(e[j]);
    }
    __shared__ float sd[8];
#pragma unroll
    for (int o = 16; o; o >>= 1) lsum += __shfl_xor_sync(0xffffffffu, lsum, o);
    if ((tid & 31) == 0) sd[tid >> 5] = lsum;
    __syncthreads();
    if (tid == 0) {
        float bsum = 0.0f;
#pragma unroll
        for (int t = 0; t < 8; t++) bsum += sd[t];
        g_inv[row] = 1.0f / bsum;
    }
}

// ---------------------------------------------------------------------------
// weights_write (per batch): fp32 weights lower triangle = e * inv.
// Runs on the side stream, overlapped with pv.
// ---------------------------------------------------------------------------
__global__ __launch_bounds__(256)
void weights_write(int b, float* __restrict__ weights) {
    const int i = blockIdx.x;
    const int row = b * SEQ + i;
    const __half* e = g_sh + (size_t)row * SEQ;
    float* w = weights + (size_t)row * SEQ;
    const int tid = threadIdx.x;
    const int n = i + 1;
    const int n4end = (n + 3) & ~3;   // zero_upper covers [n4end, SEQ)
    const float inv = g_inv[row];

    for (int j = tid; j < n4end; j += 256)
        w[j] = (j < n) ? __half2float(e[j]) * inv : 0.0f;
}

// ---------------------------------------------------------------------------
// pv (per batch): att_output = (e @ V) * inv; causal truncation at m0+BM.
// ---------------------------------------------------------------------------
__global__ __launch_bounds__(NTH)
void pv_kernel(int b, float* __restrict__ out) {
    __half* smem = (__half*)smem_raw;
    const int by = (int)gridDim.y - 1 - (int)blockIdx.y;   // reversed: big T first
    const int m0 = by * BM;
    const int n0 = blockIdx.x * BN;
    const int tid = threadIdx.x;
    const int warp = tid >> 5, lane = tid & 31;
    const int wm = warp >> 1, wn = warp & 1;

    const __half* Wt = g_sh + (size_t)b * SEQ * SEQ + (size_t)m0 * SEQ;
    const __half* V  = g_v + (size_t)b * SEQ * DOUT + n0;
    float* O = out + (size_t)b * SEQ * DOUT;
    const float* invp = g_inv + b * SEQ + m0;

    float acc[4][8][4];
    ZERO_ACC(acc);

    const int T = (m0 + BM) / BK;   // 2..32
    for (int p = 0; p < 2; p++) {
        if (p < T) {
            __half* st = smem + p * STAGE_AB;
            pf_a(st, Wt + p * BK, SEQ, tid);
            pf_b(st + A_SZH, V + (size_t)p * BK * DOUT, DOUT, tid);
        }
        cp_commit();
    }

    for (int t = 0; t < T; t++) {
        cp_wait1();
        __syncthreads();
        const __half* sc = smem + (t % NSTG) * STAGE_AB;
        COMPUTE64(sc, sc + A_SZH, 0);
        if (t + 2 < T) {
            __half* st = smem + ((t + 2) % NSTG) * STAGE_AB;
            pf_a(st, Wt + (t + 2) * BK, SEQ, tid);
            pf_b(st + A_SZH, V + (size_t)(t + 2) * BK * DOUT, DOUT, tid);
        }
        cp_commit();
    }

    const int g = lane >> 2, tig = lane & 3;
#pragma unroll
    for (int mi = 0; mi < 4; mi++) {
        int r = wm * 64 + mi * 16 + g;
        float i0 = invp[r];
        float i1 = invp[r + 8];
#pragma unroll
        for (int ni = 0; ni < 8; ni++) {
            int c = wn * 64 + ni * 8 + 2 * tig;
            *(float2*)(O + (size_t)(m0 + r) * DOUT + n0 + c) =
                make_float2(acc[mi][ni][0] * i0, acc[mi][ni][1] * i0);
            *(float2*)(O + (size_t)(m0 + r + 8) * DOUT + n0 + c) =
                make_float2(acc[mi][ni][2] * i1, acc[mi][ni][3] * i1);
        }
    }
}

// ---------------------------------------------------------------------------
extern "C" void kernel_launch(void* const* d_in, const int* in_sizes, int n_in,
                              void* d_out, int out_size) {
    const float* x  = (const float*)d_in[0];
    const float* Wq = (const float*)d_in[1];
    const float* Wk = (const float*)d_in[2];
    const float* Wv = (const float*)d_in[3];

    float* out = (float*)d_out;                                  // att_output [4,2048,1024]
    float* weights = out + (size_t)BATCH * SEQ * DOUT;           // att_weights [4,2048,2048]

    const int smem_ab = NSTG * STAGE_AB * 2;   // 107520 B
    const int smem_aa = NSTG * STAGE_AA * 2;   // 110592 B

    static cudaStream_t s1 = nullptr, s2 = nullptr;
    static cudaEvent_t evF, evX, evQK, evV, evN0, evN1, evN2, evN3, evS1, evS2;
    if (!s1) {
        cudaStreamCreateWithFlags(&s1, cudaStreamNonBlocking);
        cudaStreamCreateWithFlags(&s2, cudaStreamNonBlocking);
        cudaEventCreateWithFlags(&evF,  cudaEventDisableTiming);
        cudaEventCreateWithFlags(&evX,  cudaEventDisableTiming);
        cudaEventCreateWithFlags(&evQK, cudaEventDisableTiming);
        cudaEventCreateWithFlags(&evV,  cudaEventDisableTiming);
        cudaEventCreateWithFlags(&evN0, cudaEventDisableTiming);
        cudaEventCreateWithFlags(&evN1, cudaEventDisableTiming);
        cudaEventCreateWithFlags(&evN2, cudaEventDisableTiming);
        cudaEventCreateWithFlags(&evN3, cudaEventDisableTiming);
        cudaEventCreateWithFlags(&evS1, cudaEventDisableTiming);
        cudaEventCreateWithFlags(&evS2, cudaEventDisableTiming);
        cudaFuncSetAttribute(qkv_kernel,    cudaFuncAttributeMaxDynamicSharedMemorySize, smem_ab);
        cudaFuncSetAttribute(scores_kernel, cudaFuncAttributeMaxDynamicSharedMemorySize, smem_aa);
        cudaFuncSetAttribute(pv_kernel,     cudaFuncAttributeMaxDynamicSharedMemorySize, smem_ab);
    }

    // Fork
    cudaEventRecord(evF, 0);
    cudaStreamWaitEvent(s1, evF, 0);
    cudaStreamWaitEvent(s2, evF, 0);

    // s2: zero upper triangle (no deps). s1: convert Wv.
    zero_upper<<<BATCH * SEQ, 256, 0, s2>>>(weights);
    cvt_wv<<<(NW4 + 255) / 256, 256, 0, s1>>>(Wv);

    // main: convert x, Wq, Wk
    cvt_xqk<<<(NX4 + 2 * NW4 + 255) / 256, 256>>>(x, Wq, Wk);
    cudaEventRecord(evX, 0);

    // s1: V projection (needs xh)
    cudaStreamWaitEvent(s1, evX, 0);
    qkv_kernel<<<dim3(DOUT / BN, (BATCH * SEQ) / BM, 1), NTH, smem_ab, s1>>>(2);
    cudaEventRecord(evV, s1);

    // main: Q, K projection
    qkv_kernel<<<dim3(DOUT / BN, (BATCH * SEQ) / BM, 2), NTH, smem_ab>>>(0);
    cudaEventRecord(evQK, 0);

    // Batch pipeline: b=0,2 on main; b=1,3 on s1 (after QK done).
    scores_kernel<<<dim3(SEQ / BN, SEQ / BM, 1), NTH, smem_aa>>>(0);
    norm_light<<<SEQ, 256>>>(0);
    cudaEventRecord(evN0, 0);

    cudaStreamWaitEvent(s1, evQK, 0);
    scores_kernel<<<dim3(SEQ / BN, SEQ / BM, 1), NTH, smem_aa, s1>>>(1);
    norm_light<<<SEQ, 256, 0, s1>>>(1);
    cudaEventRecord(evN1, s1);

    scores_kernel<<<dim3(SEQ / BN, SEQ / BM, 1), NTH, smem_aa>>>(2);
    norm_light<<<SEQ, 256>>>(2);
    cudaEventRecord(evN2, 0);

    scores_kernel<<<dim3(SEQ / BN, SEQ / BM, 1), NTH, smem_aa, s1>>>(3);
    norm_light<<<SEQ, 256, 0, s1>>>(3);
    cudaEventRecord(evN3, s1);

    // pv: b=0,2 on main (needs V); b=1,3 on s1 (V in-stream).
    cudaStreamWaitEvent(0, evV, 0);
    pv_kernel<<<dim3(DOUT / BN, SEQ / BM, 1), NTH, smem_ab>>>(0, out);
    pv_kernel<<<dim3(DOUT / BN, SEQ / BM, 1), NTH, smem_ab>>>(2, out);

    pv_kernel<<<dim3(DOUT / BN, SEQ / BM, 1), NTH, smem_ab, s1>>>(1, out);
    pv_kernel<<<dim3(DOUT / BN, SEQ / BM, 1), NTH, smem_ab, s1>>>(3, out);
    cudaEventRecord(evS1, s1);

    // s2: weights writes, each after its norm; overlapped with pv.
    cudaStreamWaitEvent(s2, evN0, 0);
    weights_write<<<SEQ, 256, 0, s2>>>(0, weights);
    cudaStreamWaitEvent(s2, evN1, 0);
    weights_write<<<SEQ, 256, 0, s2>>>(1, weights);
    cudaStreamWaitEvent(s2, evN2, 0);
    weights_write<<<SEQ, 256, 0, s2>>>(2, weights);
    cudaStreamWaitEvent(s2, evN3, 0);
    weights_write<<<SEQ, 256, 0, s2>>>(3, weights);
    cudaEventRecord(evS2, s2);

    // Join
    cudaStreamWaitEvent(0, evS1, 0);
    cudaStreamWaitEvent(0, evS2, 0);
}